// round 9
// baseline (speedup 1.0000x reference)
#include <cuda_runtime.h>
#include <cstdint>
#include <math.h>

// Problem constants
#define B_  2
#define S_  2048
#define DM_ 1024
#define H_  16
#define DH_ 64

// ---------------- scratch (no allocations allowed; use __device__ globals) --
__device__ float g_qkv[B_ * S_ * 3 * DM_];        // [B*S, 3072]
__device__ float g_q[B_ * H_ * S_ * DH_];          // [BH, S, 64] rope+scale+tf32
__device__ float g_k[B_ * H_ * S_ * DH_];          // rope+tf32
__device__ float g_v[B_ * H_ * S_ * DH_];          // tf32
__device__ float g_ctx[B_ * S_ * DM_];             // [B*S, 1024] tf32, k-permuted
__device__ float g_xr[B_ * S_ * DM_];              // x  tf32, k-permuted
__device__ float g_w1[3 * DM_ * DM_];              // qkv_w tf32, k-permuted
__device__ float g_w2[DM_ * DM_];                  // proj_w tf32, k-permuted

// ---------------------------------------------------------------------------
// helpers (warp-level mma.sync — tcgen05 unavailable on base compute_103)
// ---------------------------------------------------------------------------
__device__ __forceinline__ uint32_t f2tf32(float x) {
    uint32_t r;
    asm("cvt.rna.tf32.f32 %0, %1;" : "=r"(r) : "f"(x));
    return r;
}
__device__ __forceinline__ float rt32(float x) { return __uint_as_float(f2tf32(x)); }

__device__ __forceinline__ void mma_tf32(float& c0, float& c1, float& c2, float& c3,
                                         uint32_t a0, uint32_t a1, uint32_t a2, uint32_t a3,
                                         uint32_t b0, uint32_t b1) {
    asm volatile(
        "mma.sync.aligned.m16n8k8.row.col.f32.tf32.tf32.f32 "
        "{%0,%1,%2,%3}, {%4,%5,%6,%7}, {%8,%9}, {%0,%1,%2,%3};"
        : "+f"(c0), "+f"(c1), "+f"(c2), "+f"(c3)
        : "r"(a0), "r"(a1), "r"(a2), "r"(a3), "r"(b0), "r"(b1));
}

__device__ __forceinline__ uint32_t smem_u32(const void* p) {
    uint32_t a;
    asm("{ .reg .u64 t; cvta.to.shared.u64 t, %1; cvt.u32.u64 %0, t; }" : "=r"(a) : "l"(p));
    return a;
}
__device__ __forceinline__ void cpa16(uint32_t dst, const void* src) {
    asm volatile("cp.async.cg.shared.global [%0], [%1], 16;" :: "r"(dst), "l"(src));
}
#define CP_COMMIT() asm volatile("cp.async.commit_group;" ::: "memory")
#define CP_WAIT1()  asm volatile("cp.async.wait_group 1;" ::: "memory")

// ---------------------------------------------------------------------------
// Merged prepass: tf32-round + k-permute slot(k)=2*(k&3)+(k>>2) for x, w1, w2.
// ---------------------------------------------------------------------------
#define NX8  (B_ * S_ * DM_ / 8)
#define NW18 (3 * DM_ * DM_ / 8)
#define NW28 (DM_ * DM_ / 8)

__device__ __forceinline__ void rp_one(const float* __restrict__ src,
                                       float* __restrict__ dst, int i) {
    const float4* s = (const float4*)(src + (size_t)i * 8);
    float4 lo = s[0], hi = s[1];
    float4 o0, o1;
    o0.x = rt32(lo.x);  o0.z = rt32(lo.y);
    o1.x = rt32(lo.z);  o1.z = rt32(lo.w);
    o0.y = rt32(hi.x);  o0.w = rt32(hi.y);
    o1.y = rt32(hi.z);  o1.w = rt32(hi.w);
    float4* d = (float4*)(dst + (size_t)i * 8);
    d[0] = o0; d[1] = o1;
}

__global__ void round_perm3(const float* __restrict__ x,  const float* __restrict__ w1,
                            const float* __restrict__ w2, float* __restrict__ dx,
                            float* __restrict__ dw1, float* __restrict__ dw2)
{
    int i = blockIdx.x * blockDim.x + threadIdx.x;
    if (i < NX8)              rp_one(x,  dx,  i);
    else if (i < NX8 + NW18)  rp_one(w1, dw1, i - NX8);
    else if (i < NX8 + NW18 + NW28) rp_one(w2, dw2, i - NX8 - NW18);
}

// ---------------------------------------------------------------------------
// tf32 GEMM: C[M,N] = A[M,K] @ B[N,K]^T + bias[N].
// A,B pre-rounded + k-permuted. 128x128 tile, 8 warps (64x32 each),
// cp.async 3-stage ring, ONE __syncthreads per chunk, stride 36
// (110.6KB smem -> 2 CTAs/SM), <=128 regs.
// ---------------------------------------------------------------------------
#define GST  36
#define GSTG (128 * GST)
#define GEMM_SMEM (3 * 2 * GSTG * 4)   // 110592 B

__global__ void __launch_bounds__(256, 2)
gemm_cp(const float* __restrict__ A, const float* __restrict__ Bw,
        const float* __restrict__ bias, float* __restrict__ C,
        int M, int N, int K)
{
    extern __shared__ __align__(16) float sm[];
    const uint32_t smb = smem_u32(sm);
    const int tid = threadIdx.x;
    const int wid = tid >> 5, lane = tid & 31;
    const int wm = (wid >> 2) * 64, wn = (wid & 3) * 32;
    const int lr = lane >> 2, lc = lane & 3;
    const int m0 = blockIdx.y * 128, n0 = blockIdx.x * 128;
    const int NK = K >> 5;
    const int r0 = tid >> 3, c4 = (tid & 7) * 4;

    const float* Ab = A  + (size_t)(m0 + r0) * K + c4;
    const float* Bb = Bw + (size_t)(n0 + r0) * K + c4;

    float acc[4][4][4] = {};

    auto issue = [&](int kc) {
        const int s = kc % 3;
        const uint32_t as = smb + s * 2 * GSTG * 4;
        const uint32_t bs = as + GSTG * 4;
        const int ko = kc * 32;
        #pragma unroll
        for (int it = 0; it < 4; it++) {
            const int r = r0 + it * 32;
            const uint32_t off = (r * GST + c4) * 4;
            cpa16(as + off, Ab + (size_t)(it * 32) * K + ko);
            cpa16(bs + off, Bb + (size_t)(it * 32) * K + ko);
        }
    };

    issue(0); CP_COMMIT();
    issue(1); CP_COMMIT();

    for (int kc = 0; kc < NK; kc++) {
        CP_WAIT1();
        __syncthreads();
        if (kc + 2 < NK) issue(kc + 2);
        CP_COMMIT();

        const float* Ap = sm + (kc % 3) * 2 * GSTG;
        const float* Bp = Ap + GSTG;
        #pragma unroll
        for (int ks = 0; ks < 4; ks++) {
            const int kb = ks * 8;
            uint32_t af[4][4];
            #pragma unroll
            for (int t = 0; t < 4; t++) {
                float2 lo = *(const float2*)(Ap + (wm + t * 16 + lr) * GST + kb + 2 * lc);
                float2 hi = *(const float2*)(Ap + (wm + t * 16 + 8 + lr) * GST + kb + 2 * lc);
                af[t][0] = __float_as_uint(lo.x);
                af[t][1] = __float_as_uint(hi.x);
                af[t][2] = __float_as_uint(lo.y);
                af[t][3] = __float_as_uint(hi.y);
            }
            uint32_t bf[4][2];
            #pragma unroll
            for (int j = 0; j < 4; j++) {
                float2 bb = *(const float2*)(Bp + (wn + j * 8 + lr) * GST + kb + 2 * lc);
                bf[j][0] = __float_as_uint(bb.x);
                bf[j][1] = __float_as_uint(bb.y);
            }
            #pragma unroll
            for (int t = 0; t < 4; t++)
                #pragma unroll
                for (int j = 0; j < 4; j++)
                    mma_tf32(acc[t][j][0], acc[t][j][1], acc[t][j][2], acc[t][j][3],
                             af[t][0], af[t][1], af[t][2], af[t][3],
                             bf[j][0], bf[j][1]);
        }
    }

    #pragma unroll
    for (int t = 0; t < 4; t++) {
        const int row = m0 + wm + t * 16 + lr;
        #pragma unroll
        for (int j = 0; j < 4; j++) {
            const int col = n0 + wn + j * 8 + 2 * lc;
            const float b0 = bias[col], b1 = bias[col + 1];
            float2 o0 = { acc[t][j][0] + b0, acc[t][j][1] + b1 };
            float2 o1 = { acc[t][j][2] + b0, acc[t][j][3] + b1 };
            *(float2*)(C + (size_t)row * N + col)       = o0;
            *(float2*)(C + (size_t)(row + 8) * N + col) = o1;
        }
    }
}

// ---------------------------------------------------------------------------
// RoPE + split heads. Writes q (x0.125, tf32), k (tf32), v (tf32).
// ---------------------------------------------------------------------------
__global__ void rope_split(const float* __restrict__ qkv)
{
    int idx = blockIdx.x * blockDim.x + threadIdx.x;
    int j = idx & 31;
    int t = idx >> 5;
    int h = t & (H_ - 1); t >>= 4;
    int s = t & (S_ - 1);
    int b = t >> 11;

    const float* src = qkv + (size_t)(b * S_ + s) * (3 * DM_) + h * DH_;

    float inv = expf(-(float)j * 0.287823136624f);
    float ang = (float)s * inv;
    float sn, cs;
    sincosf(ang, &sn, &cs);

    float q1 = src[j],            q2 = src[j + 32];
    float k1 = src[DM_ + j],      k2 = src[DM_ + j + 32];
    float v1 = src[2 * DM_ + j],  v2 = src[2 * DM_ + j + 32];

    size_t dst = ((size_t)(b * H_ + h) * S_ + s) * DH_;
    g_q[dst + j]      = rt32((q1 * cs - q2 * sn) * 0.125f);
    g_q[dst + j + 32] = rt32((q2 * cs + q1 * sn) * 0.125f);
    g_k[dst + j]      = rt32(k1 * cs - k2 * sn);
    g_k[dst + j + 32] = rt32(k2 * cs + k1 * sn);
    g_v[dst + j]      = rt32(v1);
    g_v[dst + j + 32] = rt32(v2);
}

// ---------------------------------------------------------------------------
// Flash attention (tf32 mma.sync, fp32 accum, causal).
// CTA: 256 q-rows x one bh, 512 threads (16 warps x 16 rows). KV tiles of 64
// in a cp.async 3-stage ring. Per-warp skip of fully-masked tiles.
// ctx written tf32 + k-permuted for the proj GEMM.
// ---------------------------------------------------------------------------
#define FST 68
#define FKV (64 * FST)
#define FLASH_SMEM ((6 * FKV + 256 * FST) * 4)   // 174080 B

__global__ void __launch_bounds__(512, 1)
flash_tc(const float* __restrict__ Qg, const float* __restrict__ Kg,
         const float* __restrict__ Vg, float* __restrict__ ctx)
{
    extern __shared__ __align__(16) float sm[];
    const uint32_t smb = smem_u32(sm);
    float* Ps = sm + 6 * FKV;           // Q staging, then per-warp P slices

    const int tid  = threadIdx.x;
    const int wid  = tid >> 5, lane = tid & 31;
    const int g    = lane >> 2, qd = lane & 3;
    const int wq0  = wid * 16;
    const int bh   = blockIdx.y;
    const int qt   = (gridDim.x - 1) - blockIdx.x;   // longest CTAs first
    const int q0   = qt * 256;

    const float* Qbase = Qg + ((size_t)bh * S_ + q0) * DH_;
    const float* Kbase = Kg + (size_t)bh * S_ * DH_;
    const float* Vbase = Vg + (size_t)bh * S_ * DH_;

    // stage Q (pre-scaled+rounded) into Ps: 256 rows
    #pragma unroll
    for (int it = 0; it < 8; it++) {
        int idx = tid + it * 512;
        int r = idx >> 4, c = (idx & 15) * 4;
        *(float4*)(Ps + r * FST + c) = *(const float4*)(Qbase + r * DH_ + c);
    }
    __syncthreads();

    uint32_t qf[8][4];
    #pragma unroll
    for (int kb = 0; kb < 8; kb++) {
        const float* b0 = Ps + (wq0 + g) * FST + kb * 8 + qd;
        qf[kb][0] = __float_as_uint(b0[0]);
        qf[kb][1] = __float_as_uint(b0[8 * FST]);
        qf[kb][2] = __float_as_uint(b0[4]);
        qf[kb][3] = __float_as_uint(b0[8 * FST + 4]);
    }
    __syncthreads();

    const int r0 = tid >> 4;             // 0..31
    const int c4 = (tid & 15) * 4;
    auto issueKV = [&](int jt) {
        const int s = jt % 3;
        const uint32_t ks_ = smb + s * 2 * FKV * 4;
        const uint32_t vs_ = ks_ + FKV * 4;
        const float* Kn = Kbase + (size_t)(jt * 64) * DH_;
        const float* Vn = Vbase + (size_t)(jt * 64) * DH_;
        #pragma unroll
        for (int it = 0; it < 2; it++) {
            const int r = r0 + it * 32;
            const uint32_t off = (r * FST + c4) * 4;
            cpa16(ks_ + off, Kn + r * DH_ + c4);
            cpa16(vs_ + off, Vn + r * DH_ + c4);
        }
    };

    const int ntiles = q0 / 64 + 4;
    issueKV(0); CP_COMMIT();
    issueKV(1); CP_COMMIT();

    float m0v = -3.0e38f, m1v = -3.0e38f, l0 = 0.f, l1 = 0.f;
    float oacc[8][4];
    #pragma unroll
    for (int nb = 0; nb < 8; nb++)
        #pragma unroll
        for (int r = 0; r < 4; r++) oacc[nb][r] = 0.f;

    const int rowa = q0 + wq0 + g;
    const int rowb = rowa + 8;
    const int rowmax = q0 + wq0 + 15;

    for (int jt = 0; jt < ntiles; jt++) {
        const int j0 = jt * 64;

        CP_WAIT1();
        __syncthreads();
        if (jt + 2 < ntiles) issueKV(jt + 2);
        CP_COMMIT();

        if (j0 > rowmax) continue;   // tile fully masked for this warp

        const float* Ks = sm + (jt % 3) * 2 * FKV;
        const float* Vs = Ks + FKV;

        float sacc[8][4];
        #pragma unroll
        for (int nb = 0; nb < 8; nb++)
            #pragma unroll
            for (int r = 0; r < 4; r++) sacc[nb][r] = 0.f;

        #pragma unroll
        for (int kb = 0; kb < 8; kb++) {
            #pragma unroll
            for (int nb = 0; nb < 8; nb++) {
                const float* bp = Ks + (nb * 8 + g) * FST + kb * 8 + qd;
                uint32_t b0 = __float_as_uint(bp[0]);
                uint32_t b1 = __float_as_uint(bp[4]);
                mma_tf32(sacc[nb][0], sacc[nb][1], sacc[nb][2], sacc[nb][3],
                         qf[kb][0], qf[kb][1], qf[kb][2], qf[kb][3], b0, b1);
            }
        }

        if (j0 + 63 > rowa) {
            #pragma unroll
            for (int nb = 0; nb < 8; nb++) {
                int col = j0 + nb * 8 + 2 * qd;
                if (col     > rowa) sacc[nb][0] = -1.0e30f;
                if (col + 1 > rowa) sacc[nb][1] = -1.0e30f;
                if (col     > rowb) sacc[nb][2] = -1.0e30f;
                if (col + 1 > rowb) sacc[nb][3] = -1.0e30f;
            }
        }

        float t0 = -3.0e38f, t1 = -3.0e38f;
        #pragma unroll
        for (int nb = 0; nb < 8; nb++) {
            t0 = fmaxf(t0, fmaxf(sacc[nb][0], sacc[nb][1]));
            t1 = fmaxf(t1, fmaxf(sacc[nb][2], sacc[nb][3]));
        }
        t0 = fmaxf(t0, __shfl_xor_sync(0xffffffffu, t0, 1));
        t0 = fmaxf(t0, __shfl_xor_sync(0xffffffffu, t0, 2));
        t1 = fmaxf(t1, __shfl_xor_sync(0xffffffffu, t1, 1));
        t1 = fmaxf(t1, __shfl_xor_sync(0xffffffffu, t1, 2));

        float mn0 = fmaxf(m0v, t0), mn1 = fmaxf(m1v, t1);
        float fac0 = __expf(m0v - mn0), fac1 = __expf(m1v - mn1);
        float rs0 = 0.f, rs1 = 0.f;

        float* prow = Ps + (wq0 + g) * FST + 2 * qd;
        #pragma unroll
        for (int nb = 0; nb < 8; nb++) {
            float p0 = __expf(sacc[nb][0] - mn0);
            float p1 = __expf(sacc[nb][1] - mn0);
            float p2 = __expf(sacc[nb][2] - mn1);
            float p3 = __expf(sacc[nb][3] - mn1);
            rs0 += p0 + p1; rs1 += p2 + p3;
            float2 w0 = { rt32(p0), rt32(p1) };
            float2 w1 = { rt32(p2), rt32(p3) };
            *(float2*)(prow + nb * 8)           = w0;
            *(float2*)(prow + nb * 8 + 8 * FST) = w1;
        }
        rs0 += __shfl_xor_sync(0xffffffffu, rs0, 1);
        rs0 += __shfl_xor_sync(0xffffffffu, rs0, 2);
        rs1 += __shfl_xor_sync(0xffffffffu, rs1, 1);
        rs1 += __shfl_xor_sync(0xffffffffu, rs1, 2);

        l0 = l0 * fac0 + rs0;  l1 = l1 * fac1 + rs1;
        m0v = mn0;  m1v = mn1;
        #pragma unroll
        for (int nb = 0; nb < 8; nb++) {
            oacc[nb][0] *= fac0; oacc[nb][1] *= fac0;
            oacc[nb][2] *= fac1; oacc[nb][3] *= fac1;
        }
        __syncwarp();

        #pragma unroll
        for (int kb = 0; kb < 8; kb++) {
            const float* pa = Ps + (wq0 + g) * FST + kb * 8 + qd;
            uint32_t a0 = __float_as_uint(pa[0]);
            uint32_t a1 = __float_as_uint(pa[8 * FST]);
            uint32_t a2 = __float_as_uint(pa[4]);
            uint32_t a3 = __float_as_uint(pa[8 * FST + 4]);
            #pragma unroll
            for (int nb = 0; nb < 8; nb++) {
                const float* vb = Vs + (kb * 8 + qd) * FST + nb * 8 + g;
                uint32_t b0 = __float_as_uint(vb[0]);
                uint32_t b1 = __float_as_uint(vb[4 * FST]);
                mma_tf32(oacc[nb][0], oacc[nb][1], oacc[nb][2], oacc[nb][3],
                         a0, a1, a2, a3, b0, b1);
            }
        }
    }

    // epilogue: ctx[b, s, perm(h*64+d)] tf32-rounded + k-permuted for proj GEMM
    const int b = bh >> 4, h = bh & 15;
    const float inv0 = 1.0f / l0, inv1 = 1.0f / l1;
    const int s0 = (qd < 2) ? 4 * qd     : 4 * qd - 7;
    const int s1 = (qd < 2) ? 4 * qd + 2 : 4 * qd - 5;
    #pragma unroll
    for (int nb = 0; nb < 8; nb++) {
        float* pa = ctx + (size_t)(b * S_ + rowa) * DM_ + h * DH_ + nb * 8;
        float* pb = ctx + (size_t)(b * S_ + rowb) * DM_ + h * DH_ + nb * 8;
        pa[s0] = rt32(oacc[nb][0] * inv0);
        pa[s1] = rt32(oacc[nb][1] * inv0);
        pb[s0] = rt32(oacc[nb][2] * inv1);
        pb[s1] = rt32(oacc[nb][3] * inv1);
    }
}

// ---------------------------------------------------------------------------
extern "C" void kernel_launch(void* const* d_in, const int* in_sizes, int n_in,
                              void* d_out, int out_size)
{
    const float* x      = (const float*)d_in[0];
    const float* qkv_w  = (const float*)d_in[1];
    const float* qkv_b  = (const float*)d_in[2];
    const float* proj_w = (const float*)d_in[3];
    const float* proj_b = (const float*)d_in[4];
    float* out = (float*)d_out;

    float *qkv_s, *q_s, *k_s, *v_s, *ctx_s, *xr_s, *w1_s, *w2_s;
    cudaGetSymbolAddress((void**)&qkv_s, g_qkv);
    cudaGetSymbolAddress((void**)&q_s,   g_q);
    cudaGetSymbolAddress((void**)&k_s,   g_k);
    cudaGetSymbolAddress((void**)&v_s,   g_v);
    cudaGetSymbolAddress((void**)&ctx_s, g_ctx);
    cudaGetSymbolAddress((void**)&xr_s,  g_xr);
    cudaGetSymbolAddress((void**)&w1_s,  g_w1);
    cudaGetSymbolAddress((void**)&w2_s,  g_w2);

    cudaFuncSetAttribute(gemm_cp,  cudaFuncAttributeMaxDynamicSharedMemorySize, GEMM_SMEM);
    cudaFuncSetAttribute(flash_tc, cudaFuncAttributeMaxDynamicSharedMemorySize, FLASH_SMEM);

    // 0) pre-round (tf32) + k-permute all GEMM operands in one launch
    {
        int total = NX8 + NW18 + NW28;
        round_perm3<<<(total + 255) / 256, 256>>>(x, qkv_w, proj_w, xr_s, w1_s, w2_s);
    }

    // 1) QKV projection
    {
        dim3 grid(3 * DM_ / 128, B_ * S_ / 128);
        gemm_cp<<<grid, 256, GEMM_SMEM>>>(xr_s, w1_s, qkv_b, qkv_s, B_ * S_, 3 * DM_, DM_);
    }

    // 2) RoPE + head split
    {
        int total = B_ * S_ * H_ * 32;
        rope_split<<<total / 256, 256>>>(qkv_s);
    }

    // 3) Causal flash attention (512 threads, 256 q-rows per CTA)
    {
        dim3 grid(S_ / 256, B_ * H_);
        flash_tc<<<grid, 512, FLASH_SMEM>>>(q_s, k_s, v_s, ctx_s);
    }

    // 4) Output projection
    {
        dim3 grid(DM_ / 128, B_ * S_ / 128);
        gemm_cp<<<grid, 256, GEMM_SMEM>>>(ctx_s, w2_s, proj_b, out, B_ * S_, DM_, DM_);
    }
}

// round 10
// speedup vs baseline: 1.0354x; 1.0354x over previous
#include <cuda_runtime.h>
#include <cstdint>
#include <math.h>

// Problem constants
#define B_  2
#define S_  2048
#define DM_ 1024
#define H_  16
#define DH_ 64

// ---------------- scratch (no allocations allowed; use __device__ globals) --
__device__ float g_qkv[B_ * S_ * 3 * DM_];        // [B*S, 3072]
__device__ float g_q[B_ * H_ * S_ * DH_];          // [BH, S, 64] rope+scale+tf32
__device__ float g_k[B_ * H_ * S_ * DH_];          // rope+tf32
__device__ float g_v[B_ * H_ * S_ * DH_];          // tf32
__device__ float g_ctx[B_ * S_ * DM_];             // [B*S, 1024] tf32, k-permuted
__device__ float g_xr[B_ * S_ * DM_];              // x  tf32, k-permuted
__device__ float g_w1[3 * DM_ * DM_];              // qkv_w tf32, k-permuted
__device__ float g_w2[DM_ * DM_];                  // proj_w tf32, k-permuted

// ---------------------------------------------------------------------------
// helpers (warp-level mma.sync — tcgen05 unavailable on base compute_103)
// ---------------------------------------------------------------------------
__device__ __forceinline__ uint32_t f2tf32(float x) {
    uint32_t r;
    asm("cvt.rna.tf32.f32 %0, %1;" : "=r"(r) : "f"(x));
    return r;
}
__device__ __forceinline__ float rt32(float x) { return __uint_as_float(f2tf32(x)); }

__device__ __forceinline__ void mma_tf32(float& c0, float& c1, float& c2, float& c3,
                                         uint32_t a0, uint32_t a1, uint32_t a2, uint32_t a3,
                                         uint32_t b0, uint32_t b1) {
    asm volatile(
        "mma.sync.aligned.m16n8k8.row.col.f32.tf32.tf32.f32 "
        "{%0,%1,%2,%3}, {%4,%5,%6,%7}, {%8,%9}, {%0,%1,%2,%3};"
        : "+f"(c0), "+f"(c1), "+f"(c2), "+f"(c3)
        : "r"(a0), "r"(a1), "r"(a2), "r"(a3), "r"(b0), "r"(b1));
}

__device__ __forceinline__ uint32_t smem_u32(const void* p) {
    uint32_t a;
    asm("{ .reg .u64 t; cvta.to.shared.u64 t, %1; cvt.u32.u64 %0, t; }" : "=r"(a) : "l"(p));
    return a;
}
__device__ __forceinline__ void cpa16(uint32_t dst, const void* src) {
    asm volatile("cp.async.cg.shared.global [%0], [%1], 16;" :: "r"(dst), "l"(src));
}
#define CP_COMMIT() asm volatile("cp.async.commit_group;" ::: "memory")
#define CP_WAIT1()  asm volatile("cp.async.wait_group 1;" ::: "memory")

// ---------------------------------------------------------------------------
// Merged prepass: tf32-round + k-permute slot(k)=2*(k&3)+(k>>2) for x, w1, w2.
// ---------------------------------------------------------------------------
#define NX8  (B_ * S_ * DM_ / 8)
#define NW18 (3 * DM_ * DM_ / 8)
#define NW28 (DM_ * DM_ / 8)

__device__ __forceinline__ void rp_one(const float* __restrict__ src,
                                       float* __restrict__ dst, int i) {
    const float4* s = (const float4*)(src + (size_t)i * 8);
    float4 lo = s[0], hi = s[1];
    float4 o0, o1;
    o0.x = rt32(lo.x);  o0.z = rt32(lo.y);
    o1.x = rt32(lo.z);  o1.z = rt32(lo.w);
    o0.y = rt32(hi.x);  o0.w = rt32(hi.y);
    o1.y = rt32(hi.z);  o1.w = rt32(hi.w);
    float4* d = (float4*)(dst + (size_t)i * 8);
    d[0] = o0; d[1] = o1;
}

__global__ void round_perm3(const float* __restrict__ x,  const float* __restrict__ w1,
                            const float* __restrict__ w2, float* __restrict__ dx,
                            float* __restrict__ dw1, float* __restrict__ dw2)
{
    int i = blockIdx.x * blockDim.x + threadIdx.x;
    if (i < NX8)              rp_one(x,  dx,  i);
    else if (i < NX8 + NW18)  rp_one(w1, dw1, i - NX8);
    else if (i < NX8 + NW18 + NW28) rp_one(w2, dw2, i - NX8 - NW18);
}

// ---------------------------------------------------------------------------
// tf32 GEMM (unchanged from R9): 128x128 tile, 8 warps, cp.async 3-stage
// ring, one sync per chunk, stride 36 (110.6KB -> 2 CTAs/SM).
// ---------------------------------------------------------------------------
#define GST  36
#define GSTG (128 * GST)
#define GEMM_SMEM (3 * 2 * GSTG * 4)   // 110592 B

__global__ void __launch_bounds__(256, 2)
gemm_cp(const float* __restrict__ A, const float* __restrict__ Bw,
        const float* __restrict__ bias, float* __restrict__ C,
        int M, int N, int K)
{
    extern __shared__ __align__(16) float sm[];
    const uint32_t smb = smem_u32(sm);
    const int tid = threadIdx.x;
    const int wid = tid >> 5, lane = tid & 31;
    const int wm = (wid >> 2) * 64, wn = (wid & 3) * 32;
    const int lr = lane >> 2, lc = lane & 3;
    const int m0 = blockIdx.y * 128, n0 = blockIdx.x * 128;
    const int NK = K >> 5;
    const int r0 = tid >> 3, c4 = (tid & 7) * 4;

    const float* Ab = A  + (size_t)(m0 + r0) * K + c4;
    const float* Bb = Bw + (size_t)(n0 + r0) * K + c4;

    float acc[4][4][4] = {};

    auto issue = [&](int kc) {
        const int s = kc % 3;
        const uint32_t as = smb + s * 2 * GSTG * 4;
        const uint32_t bs = as + GSTG * 4;
        const int ko = kc * 32;
        #pragma unroll
        for (int it = 0; it < 4; it++) {
            const int r = r0 + it * 32;
            const uint32_t off = (r * GST + c4) * 4;
            cpa16(as + off, Ab + (size_t)(it * 32) * K + ko);
            cpa16(bs + off, Bb + (size_t)(it * 32) * K + ko);
        }
    };

    issue(0); CP_COMMIT();
    issue(1); CP_COMMIT();

    for (int kc = 0; kc < NK; kc++) {
        CP_WAIT1();
        __syncthreads();
        if (kc + 2 < NK) issue(kc + 2);
        CP_COMMIT();

        const float* Ap = sm + (kc % 3) * 2 * GSTG;
        const float* Bp = Ap + GSTG;
        #pragma unroll
        for (int ks = 0; ks < 4; ks++) {
            const int kb = ks * 8;
            uint32_t af[4][4];
            #pragma unroll
            for (int t = 0; t < 4; t++) {
                float2 lo = *(const float2*)(Ap + (wm + t * 16 + lr) * GST + kb + 2 * lc);
                float2 hi = *(const float2*)(Ap + (wm + t * 16 + 8 + lr) * GST + kb + 2 * lc);
                af[t][0] = __float_as_uint(lo.x);
                af[t][1] = __float_as_uint(hi.x);
                af[t][2] = __float_as_uint(lo.y);
                af[t][3] = __float_as_uint(hi.y);
            }
            uint32_t bf[4][2];
            #pragma unroll
            for (int j = 0; j < 4; j++) {
                float2 bb = *(const float2*)(Bp + (wn + j * 8 + lr) * GST + kb + 2 * lc);
                bf[j][0] = __float_as_uint(bb.x);
                bf[j][1] = __float_as_uint(bb.y);
            }
            #pragma unroll
            for (int t = 0; t < 4; t++)
                #pragma unroll
                for (int j = 0; j < 4; j++)
                    mma_tf32(acc[t][j][0], acc[t][j][1], acc[t][j][2], acc[t][j][3],
                             af[t][0], af[t][1], af[t][2], af[t][3],
                             bf[j][0], bf[j][1]);
        }
    }

    #pragma unroll
    for (int t = 0; t < 4; t++) {
        const int row = m0 + wm + t * 16 + lr;
        #pragma unroll
        for (int j = 0; j < 4; j++) {
            const int col = n0 + wn + j * 8 + 2 * lc;
            const float b0 = bias[col], b1 = bias[col + 1];
            float2 o0 = { acc[t][j][0] + b0, acc[t][j][1] + b1 };
            float2 o1 = { acc[t][j][2] + b0, acc[t][j][3] + b1 };
            *(float2*)(C + (size_t)row * N + col)       = o0;
            *(float2*)(C + (size_t)(row + 8) * N + col) = o1;
        }
    }
}

// ---------------------------------------------------------------------------
// RoPE + split heads. Writes q (x0.125, tf32), k (tf32), v (tf32).
// ---------------------------------------------------------------------------
__global__ void rope_split(const float* __restrict__ qkv)
{
    int idx = blockIdx.x * blockDim.x + threadIdx.x;
    int j = idx & 31;
    int t = idx >> 5;
    int h = t & (H_ - 1); t >>= 4;
    int s = t & (S_ - 1);
    int b = t >> 11;

    const float* src = qkv + (size_t)(b * S_ + s) * (3 * DM_) + h * DH_;

    float inv = expf(-(float)j * 0.287823136624f);
    float ang = (float)s * inv;
    float sn, cs;
    sincosf(ang, &sn, &cs);

    float q1 = src[j],            q2 = src[j + 32];
    float k1 = src[DM_ + j],      k2 = src[DM_ + j + 32];
    float v1 = src[2 * DM_ + j],  v2 = src[2 * DM_ + j + 32];

    size_t dst = ((size_t)(b * H_ + h) * S_ + s) * DH_;
    g_q[dst + j]      = rt32((q1 * cs - q2 * sn) * 0.125f);
    g_q[dst + j + 32] = rt32((q2 * cs + q1 * sn) * 0.125f);
    g_k[dst + j]      = rt32(k1 * cs - k2 * sn);
    g_k[dst + j + 32] = rt32(k2 * cs + k1 * sn);
    g_v[dst + j]      = rt32(v1);
    g_v[dst + j + 32] = rt32(v2);
}

// ---------------------------------------------------------------------------
// Flash attention (tf32 mma.sync, fp32 accum, causal).
// CTA: 128 q-rows x one bh, 256 threads (8 warps x 16 rows). KV tiles of 64
// in a cp.async 2-STAGE ring -> 104.4KB smem -> 2 CTAs/SM (the win of R8
// applied here). ctx written tf32 + k-permuted for the proj GEMM.
// ---------------------------------------------------------------------------
#define FST 68
#define FKV (64 * FST)
#define FLASH_SMEM ((4 * FKV + 128 * FST) * 4)   // 104448 B

__global__ void __launch_bounds__(256, 2)
flash_tc(const float* __restrict__ Qg, const float* __restrict__ Kg,
         const float* __restrict__ Vg, float* __restrict__ ctx)
{
    extern __shared__ __align__(16) float sm[];
    const uint32_t smb = smem_u32(sm);
    float* Ps = sm + 4 * FKV;           // Q staging, then per-warp P slices

    const int tid  = threadIdx.x;
    const int wid  = tid >> 5, lane = tid & 31;
    const int g    = lane >> 2, qd = lane & 3;
    const int wq0  = wid * 16;
    const int bh   = blockIdx.y;
    const int qt   = (gridDim.x - 1) - blockIdx.x;   // longest CTAs first
    const int q0   = qt * 128;

    const float* Qbase = Qg + ((size_t)bh * S_ + q0) * DH_;
    const float* Kbase = Kg + (size_t)bh * S_ * DH_;
    const float* Vbase = Vg + (size_t)bh * S_ * DH_;

    // stage Q (pre-scaled+rounded) into Ps
    #pragma unroll
    for (int it = 0; it < 8; it++) {
        int idx = tid + it * 256;
        int r = idx >> 4, c = (idx & 15) * 4;
        *(float4*)(Ps + r * FST + c) = *(const float4*)(Qbase + r * DH_ + c);
    }
    __syncthreads();

    uint32_t qf[8][4];
    #pragma unroll
    for (int kb = 0; kb < 8; kb++) {
        const float* b0 = Ps + (wq0 + g) * FST + kb * 8 + qd;
        qf[kb][0] = __float_as_uint(b0[0]);
        qf[kb][1] = __float_as_uint(b0[8 * FST]);
        qf[kb][2] = __float_as_uint(b0[4]);
        qf[kb][3] = __float_as_uint(b0[8 * FST + 4]);
    }
    __syncthreads();

    const int r0 = tid >> 4;             // 0..15
    const int c4 = (tid & 15) * 4;
    auto issueKV = [&](int jt) {
        const int s = jt & 1;
        const uint32_t ks_ = smb + s * 2 * FKV * 4;
        const uint32_t vs_ = ks_ + FKV * 4;
        const float* Kn = Kbase + (size_t)(jt * 64) * DH_;
        const float* Vn = Vbase + (size_t)(jt * 64) * DH_;
        #pragma unroll
        for (int it = 0; it < 4; it++) {
            const int r = r0 + it * 16;
            const uint32_t off = (r * FST + c4) * 4;
            cpa16(ks_ + off, Kn + r * DH_ + c4);
            cpa16(vs_ + off, Vn + r * DH_ + c4);
        }
    };

    const int ntiles = q0 / 64 + 2;
    issueKV(0); CP_COMMIT();

    float m0v = -3.0e38f, m1v = -3.0e38f, l0 = 0.f, l1 = 0.f;
    float oacc[8][4];
    #pragma unroll
    for (int nb = 0; nb < 8; nb++)
        #pragma unroll
        for (int r = 0; r < 4; r++) oacc[nb][r] = 0.f;

    const int rowa = q0 + wq0 + g;
    const int rowb = rowa + 8;
    const int rowmax = q0 + wq0 + 15;

    for (int jt = 0; jt < ntiles; jt++) {
        const int j0 = jt * 64;

        if (jt + 1 < ntiles) issueKV(jt + 1);
        CP_COMMIT();
        CP_WAIT1();
        __syncthreads();                       // tile jt visible

        if (j0 <= rowmax) {                    // not fully masked for this warp
            const float* Ks = sm + (jt & 1) * 2 * FKV;
            const float* Vs = Ks + FKV;

            float sacc[8][4];
            #pragma unroll
            for (int nb = 0; nb < 8; nb++)
                #pragma unroll
                for (int r = 0; r < 4; r++) sacc[nb][r] = 0.f;

            #pragma unroll
            for (int kb = 0; kb < 8; kb++) {
                #pragma unroll
                for (int nb = 0; nb < 8; nb++) {
                    const float* bp = Ks + (nb * 8 + g) * FST + kb * 8 + qd;
                    uint32_t b0 = __float_as_uint(bp[0]);
                    uint32_t b1 = __float_as_uint(bp[4]);
                    mma_tf32(sacc[nb][0], sacc[nb][1], sacc[nb][2], sacc[nb][3],
                             qf[kb][0], qf[kb][1], qf[kb][2], qf[kb][3], b0, b1);
                }
            }

            if (j0 + 63 > rowa) {
                #pragma unroll
                for (int nb = 0; nb < 8; nb++) {
                    int col = j0 + nb * 8 + 2 * qd;
                    if (col     > rowa) sacc[nb][0] = -1.0e30f;
                    if (col + 1 > rowa) sacc[nb][1] = -1.0e30f;
                    if (col     > rowb) sacc[nb][2] = -1.0e30f;
                    if (col + 1 > rowb) sacc[nb][3] = -1.0e30f;
                }
            }

            float t0 = -3.0e38f, t1 = -3.0e38f;
            #pragma unroll
            for (int nb = 0; nb < 8; nb++) {
                t0 = fmaxf(t0, fmaxf(sacc[nb][0], sacc[nb][1]));
                t1 = fmaxf(t1, fmaxf(sacc[nb][2], sacc[nb][3]));
            }
            t0 = fmaxf(t0, __shfl_xor_sync(0xffffffffu, t0, 1));
            t0 = fmaxf(t0, __shfl_xor_sync(0xffffffffu, t0, 2));
            t1 = fmaxf(t1, __shfl_xor_sync(0xffffffffu, t1, 1));
            t1 = fmaxf(t1, __shfl_xor_sync(0xffffffffu, t1, 2));

            float mn0 = fmaxf(m0v, t0), mn1 = fmaxf(m1v, t1);
            float fac0 = __expf(m0v - mn0), fac1 = __expf(m1v - mn1);
            float rs0 = 0.f, rs1 = 0.f;

            float* prow = Ps + (wq0 + g) * FST + 2 * qd;
            #pragma unroll
            for (int nb = 0; nb < 8; nb++) {
                float p0 = __expf(sacc[nb][0] - mn0);
                float p1 = __expf(sacc[nb][1] - mn0);
                float p2 = __expf(sacc[nb][2] - mn1);
                float p3 = __expf(sacc[nb][3] - mn1);
                rs0 += p0 + p1; rs1 += p2 + p3;
                float2 w0 = { rt32(p0), rt32(p1) };
                float2 w1 = { rt32(p2), rt32(p3) };
                *(float2*)(prow + nb * 8)           = w0;
                *(float2*)(prow + nb * 8 + 8 * FST) = w1;
            }
            rs0 += __shfl_xor_sync(0xffffffffu, rs0, 1);
            rs0 += __shfl_xor_sync(0xffffffffu, rs0, 2);
            rs1 += __shfl_xor_sync(0xffffffffu, rs1, 1);
            rs1 += __shfl_xor_sync(0xffffffffu, rs1, 2);

            l0 = l0 * fac0 + rs0;  l1 = l1 * fac1 + rs1;
            m0v = mn0;  m1v = mn1;
            #pragma unroll
            for (int nb = 0; nb < 8; nb++) {
                oacc[nb][0] *= fac0; oacc[nb][1] *= fac0;
                oacc[nb][2] *= fac1; oacc[nb][3] *= fac1;
            }
            __syncwarp();

            #pragma unroll
            for (int kb = 0; kb < 8; kb++) {
                const float* pa = Ps + (wq0 + g) * FST + kb * 8 + qd;
                uint32_t a0 = __float_as_uint(pa[0]);
                uint32_t a1 = __float_as_uint(pa[8 * FST]);
                uint32_t a2 = __float_as_uint(pa[4]);
                uint32_t a3 = __float_as_uint(pa[8 * FST + 4]);
                #pragma unroll
                for (int nb = 0; nb < 8; nb++) {
                    const float* vb = Vs + (kb * 8 + qd) * FST + nb * 8 + g;
                    uint32_t b0 = __float_as_uint(vb[0]);
                    uint32_t b1 = __float_as_uint(vb[4 * FST]);
                    mma_tf32(oacc[nb][0], oacc[nb][1], oacc[nb][2], oacc[nb][3],
                             a0, a1, a2, a3, b0, b1);
                }
            }
        }
        __syncthreads();                       // buffer jt&1 free for reuse
    }

    // epilogue: ctx[b, s, perm(h*64+d)] tf32-rounded + k-permuted for proj GEMM
    const int b = bh >> 4, h = bh & 15;
    const float inv0 = 1.0f / l0, inv1 = 1.0f / l1;
    const int s0 = (qd < 2) ? 4 * qd     : 4 * qd - 7;
    const int s1 = (qd < 2) ? 4 * qd + 2 : 4 * qd - 5;
    #pragma unroll
    for (int nb = 0; nb < 8; nb++) {
        float* pa = ctx + (size_t)(b * S_ + rowa) * DM_ + h * DH_ + nb * 8;
        float* pb = ctx + (size_t)(b * S_ + rowb) * DM_ + h * DH_ + nb * 8;
        pa[s0] = rt32(oacc[nb][0] * inv0);
        pa[s1] = rt32(oacc[nb][1] * inv0);
        pb[s0] = rt32(oacc[nb][2] * inv1);
        pb[s1] = rt32(oacc[nb][3] * inv1);
    }
}

// ---------------------------------------------------------------------------
extern "C" void kernel_launch(void* const* d_in, const int* in_sizes, int n_in,
                              void* d_out, int out_size)
{
    const float* x      = (const float*)d_in[0];
    const float* qkv_w  = (const float*)d_in[1];
    const float* qkv_b  = (const float*)d_in[2];
    const float* proj_w = (const float*)d_in[3];
    const float* proj_b = (const float*)d_in[4];
    float* out = (float*)d_out;

    float *qkv_s, *q_s, *k_s, *v_s, *ctx_s, *xr_s, *w1_s, *w2_s;
    cudaGetSymbolAddress((void**)&qkv_s, g_qkv);
    cudaGetSymbolAddress((void**)&q_s,   g_q);
    cudaGetSymbolAddress((void**)&k_s,   g_k);
    cudaGetSymbolAddress((void**)&v_s,   g_v);
    cudaGetSymbolAddress((void**)&ctx_s, g_ctx);
    cudaGetSymbolAddress((void**)&xr_s,  g_xr);
    cudaGetSymbolAddress((void**)&w1_s,  g_w1);
    cudaGetSymbolAddress((void**)&w2_s,  g_w2);

    cudaFuncSetAttribute(gemm_cp,  cudaFuncAttributeMaxDynamicSharedMemorySize, GEMM_SMEM);
    cudaFuncSetAttribute(flash_tc, cudaFuncAttributeMaxDynamicSharedMemorySize, FLASH_SMEM);

    // 0) pre-round (tf32) + k-permute all GEMM operands in one launch
    {
        int total = NX8 + NW18 + NW28;
        round_perm3<<<(total + 255) / 256, 256>>>(x, qkv_w, proj_w, xr_s, w1_s, w2_s);
    }

    // 1) QKV projection
    {
        dim3 grid(3 * DM_ / 128, B_ * S_ / 128);
        gemm_cp<<<grid, 256, GEMM_SMEM>>>(xr_s, w1_s, qkv_b, qkv_s, B_ * S_, 3 * DM_, DM_);
    }

    // 2) RoPE + head split
    {
        int total = B_ * S_ * H_ * 32;
        rope_split<<<total / 256, 256>>>(qkv_s);
    }

    // 3) Causal flash attention (128 q-rows, 256 threads, 2 CTAs/SM)
    {
        dim3 grid(S_ / 128, B_ * H_);
        flash_tc<<<grid, 256, FLASH_SMEM>>>(q_s, k_s, v_s, ctx_s);
    }

    // 4) Output projection
    {
        dim3 grid(DM_ / 128, B_ * S_ / 128);
        gemm_cp<<<grid, 256, GEMM_SMEM>>>(ctx_s, w2_s, proj_b, out, B_ * S_, DM_, DM_);
    }
}